// round 12
// baseline (speedup 1.0000x reference)
#include <cuda_runtime.h>
#include <cstdint>

// ---------------- problem constants ----------------
#define BATCH   32
#define HH      56
#define WW      56
#define CC      256
#define HEADS   8
#define HD      32
#define WIN     7
#define SHIFT   3
#define NN      49
#define NWIN    64
#define NWTOT   (BATCH * NWIN)      // 2048
#define MTOT    (NWTOT * NN)        // 100352

// ---------------- scratch (device globals; device-code refs only) ----------------
__device__ float g_qkv[(size_t)MTOT * 768];
__device__ float g_att[(size_t)MTOT * 256];
__device__ float g_bias[4 * HEADS * NN * 52];

// Map a flattened window-row index m -> element offset of the source pixel in x.
// roll(+3) inverts roll(-3): same map serves gather (QKV) and scatter (proj).
__device__ __forceinline__ int src_offset(int m) {
    int wq = m / NN;
    int n  = m - wq * NN;
    int b  = wq >> 6;
    int wi = wq & 63;
    int wh = wi >> 3, ww = wi & 7;
    int r = wh * WIN + n / WIN;
    int c = ww * WIN + n % WIN;
    int sh = r + SHIFT; if (sh >= HH) sh -= HH;
    int sw = c + SHIFT; if (sw >= WW) sw -= WW;
    return ((b * HH + sh) * WW + sw) * CC;
}

// =====================================================================
// Kernel 0: fused bias+mask table. 4 classes x 8 heads.
// =====================================================================
__global__ void bias_kernel(const float* __restrict__ tbl,
                            const int* __restrict__ relidx) {
    const int cls = blockIdx.x & 3;
    const int h   = blockIdx.x >> 2;
    for (int idx = threadIdx.x; idx < NN * NN; idx += blockDim.x) {
        int i = idx / NN, j = idx % NN;
        float b = tbl[relidx[idx] * HEADS + h];
        int rhi = (cls & 2) ? ((i / 7 < 4) ? 1 : 2) : 0;
        int rwi = (cls & 1) ? ((i % 7 < 4) ? 1 : 2) : 0;
        int rhj = (cls & 2) ? ((j / 7 < 4) ? 1 : 2) : 0;
        int rwj = (cls & 1) ? ((j % 7 < 4) ? 1 : 2) : 0;
        float msk = ((rhi * 3 + rwi) == (rhj * 3 + rwj)) ? 0.f : -100.f;
        g_bias[((cls * HEADS + h) * NN + i) * 52 + j] = b + msk;
    }
}

// =====================================================================
// 128x128x16 fp32 SGEMM, 256 threads, split 8x8 microtile (conflict-free
// LDS: quarter-warp B-fetch = one 128B segment), double-buffered smem.
// (Proven config: R4 measured qkv=810us, proj=272us, fma=60.5%.)
//   QKV=true : A = X (gathered via so[]), C = g_qkv (ldc=768)
//   QKV=false: A = g_att (linear),        C = OUT (scattered via so[])
// =====================================================================
template<bool QKV>
__global__ __launch_bounds__(256) void gemm128(const float* __restrict__ X,
                                               const float* __restrict__ W,
                                               const float* __restrict__ bias,
                                               float* __restrict__ OUT) {
    __shared__ float As[2][16][132];
    __shared__ float Bs[2][16][132];
    __shared__ int so[128];

    const int n0 = blockIdx.x * 128;
    const int m0 = blockIdx.y * 128;
    const int t  = threadIdx.x;

    if (t < 128) so[t] = src_offset(m0 + t);
    __syncthreads();

    // ---- load mapping ----
    const int r  = t >> 2;            // 0..63
    const int kq = t & 3;             // 0..3

    const float* ap0;
    const float* ap1;
    if (QKV) {
        ap0 = X + so[r]      + kq * 4;
        ap1 = X + so[r + 64] + kq * 4;
    } else {
        ap0 = g_att + (size_t)(m0 + r)      * 256 + kq * 4;
        ap1 = g_att + (size_t)(m0 + r + 64) * 256 + kq * 4;
    }
    const float* bp0 = W + (size_t)(n0 + r)      * CC + kq * 4;
    const float* bp1 = W + (size_t)(n0 + r + 64) * CC + kq * 4;

    // ---- compute mapping: split microtile ----
    const int tx4 = (t & 15) * 4;
    const int ty4 = (t >> 4) * 4;

    float acc[8][8];
#pragma unroll
    for (int i = 0; i < 8; i++)
#pragma unroll
        for (int j = 0; j < 8; j++) acc[i][j] = 0.f;

    // ---- prologue ----
    float4 ra0 = *(const float4*)ap0;
    float4 ra1 = *(const float4*)ap1;
    float4 rb0 = *(const float4*)bp0;
    float4 rb1 = *(const float4*)bp1;

    int buf = 0;
    {
        As[0][kq * 4 + 0][r] = ra0.x; As[0][kq * 4 + 1][r] = ra0.y;
        As[0][kq * 4 + 2][r] = ra0.z; As[0][kq * 4 + 3][r] = ra0.w;
        As[0][kq * 4 + 0][r + 64] = ra1.x; As[0][kq * 4 + 1][r + 64] = ra1.y;
        As[0][kq * 4 + 2][r + 64] = ra1.z; As[0][kq * 4 + 3][r + 64] = ra1.w;
        Bs[0][kq * 4 + 0][r] = rb0.x; Bs[0][kq * 4 + 1][r] = rb0.y;
        Bs[0][kq * 4 + 2][r] = rb0.z; Bs[0][kq * 4 + 3][r] = rb0.w;
        Bs[0][kq * 4 + 0][r + 64] = rb1.x; Bs[0][kq * 4 + 1][r + 64] = rb1.y;
        Bs[0][kq * 4 + 2][r + 64] = rb1.z; Bs[0][kq * 4 + 3][r + 64] = rb1.w;
    }
    __syncthreads();

#pragma unroll 1
    for (int it = 0; it < 16; ++it) {
        if (it < 15) {
            const int k0 = (it + 1) * 16;
            ra0 = *(const float4*)(ap0 + k0);
            ra1 = *(const float4*)(ap1 + k0);
            rb0 = *(const float4*)(bp0 + k0);
            rb1 = *(const float4*)(bp1 + k0);
        }

#pragma unroll
        for (int k = 0; k < 16; k++) {
            float4 av0 = *(const float4*)&As[buf][k][ty4];
            float4 av1 = *(const float4*)&As[buf][k][ty4 + 64];
            float4 bv0 = *(const float4*)&Bs[buf][k][tx4];
            float4 bv1 = *(const float4*)&Bs[buf][k][tx4 + 64];
            float a[8] = {av0.x, av0.y, av0.z, av0.w, av1.x, av1.y, av1.z, av1.w};
            float b[8] = {bv0.x, bv0.y, bv0.z, bv0.w, bv1.x, bv1.y, bv1.z, bv1.w};
#pragma unroll
            for (int i = 0; i < 8; i++)
#pragma unroll
                for (int j = 0; j < 8; j++) acc[i][j] += a[i] * b[j];
        }

        if (it < 15) {
            const int nb = buf ^ 1;
            As[nb][kq * 4 + 0][r] = ra0.x; As[nb][kq * 4 + 1][r] = ra0.y;
            As[nb][kq * 4 + 2][r] = ra0.z; As[nb][kq * 4 + 3][r] = ra0.w;
            As[nb][kq * 4 + 0][r + 64] = ra1.x; As[nb][kq * 4 + 1][r + 64] = ra1.y;
            As[nb][kq * 4 + 2][r + 64] = ra1.z; As[nb][kq * 4 + 3][r + 64] = ra1.w;
            Bs[nb][kq * 4 + 0][r] = rb0.x; Bs[nb][kq * 4 + 1][r] = rb0.y;
            Bs[nb][kq * 4 + 2][r] = rb0.z; Bs[nb][kq * 4 + 3][r] = rb0.w;
            Bs[nb][kq * 4 + 0][r + 64] = rb1.x; Bs[nb][kq * 4 + 1][r + 64] = rb1.y;
            Bs[nb][kq * 4 + 2][r + 64] = rb1.z; Bs[nb][kq * 4 + 3][r + 64] = rb1.w;
            __syncthreads();
            buf = nb;
        }
    }

    // ---- epilogue ----
    float4 bb0 = *(const float4*)(bias + n0 + tx4);
    float4 bb1 = *(const float4*)(bias + n0 + 64 + tx4);
#pragma unroll
    for (int i = 0; i < 8; i++) {
        const int mr = (i < 4) ? (ty4 + i) : (64 + ty4 + i - 4);
        float* base;
        if (QKV) base = g_qkv + (size_t)(m0 + mr) * 768 + n0;
        else     base = OUT + so[mr] + n0;
        float4 o0, o1;
        o0.x = acc[i][0] + bb0.x; o0.y = acc[i][1] + bb0.y;
        o0.z = acc[i][2] + bb0.z; o0.w = acc[i][3] + bb0.w;
        o1.x = acc[i][4] + bb1.x; o1.y = acc[i][5] + bb1.y;
        o1.z = acc[i][6] + bb1.z; o1.w = acc[i][7] + bb1.w;
        *(float4*)(base + tx4)      = o0;
        *(float4*)(base + 64 + tx4) = o1;
    }
}

// =====================================================================
// Kernel 2: windowed attention. One block per (window, head).
// Score phase: q row in registers, LDS.64 kT pairs. PV: d-pairs.
// =====================================================================
__global__ __launch_bounds__(256) void attn_kernel() {
    __shared__ float qs[NN * HD];
    __shared__ float vs[NN * HD];
    __shared__ float kT[HD * 56];
    __shared__ float sS[NN * 52];

    const int w = blockIdx.x >> 3;
    const int h = blockIdx.x & 7;
    const int t = threadIdx.x;

    const int wi = w & 63;
    const int cls = (((wi >> 3) == 7) ? 2 : 0) | (((wi & 7) == 7) ? 1 : 0);
    const float* gb = g_bias + (size_t)((cls * HEADS + h) * NN) * 52;

    const float* base = g_qkv + (size_t)w * NN * 768 + h * HD;
    for (int idx = t; idx < NN * 8; idx += 256) {
        int n = idx >> 3, dq = idx & 7;
        const float4* p = (const float4*)(base + n * 768 + dq * 4);
        float4 q4 = p[0];
        float4 k4 = p[64];
        float4 v4 = p[128];
        *(float4*)&qs[n * HD + dq * 4] = q4;
        *(float4*)&vs[n * HD + dq * 4] = v4;
        kT[(dq * 4 + 0) * 56 + n] = k4.x;
        kT[(dq * 4 + 1) * 56 + n] = k4.y;
        kT[(dq * 4 + 2) * 56 + n] = k4.z;
        kT[(dq * 4 + 3) * 56 + n] = k4.w;
    }
    __syncthreads();

    // ---- scores: warp w8 -> rows {w8, w8+8, ...}; lane -> j-pair ----
    const int lane = t & 31, w8 = t >> 5;
    const int j = lane * 2;
    const float scale = 0.17677669529663687f;
    for (int i = w8; i < NN; i += 8) {
        float q[HD];
#pragma unroll
        for (int kq = 0; kq < HD / 4; kq++) {
            float4 v4 = *(const float4*)&qs[i * HD + kq * 4];   // broadcast
            q[kq * 4] = v4.x; q[kq * 4 + 1] = v4.y;
            q[kq * 4 + 2] = v4.z; q[kq * 4 + 3] = v4.w;
        }
        if (j < NN) {
            float ax = 0.f, ay = 0.f;
#pragma unroll
            for (int k = 0; k < HD; k++) {
                float2 kv = *(const float2*)&kT[k * 56 + j];
                ax += q[k] * kv.x;
                ay += q[k] * kv.y;
            }
            sS[i * 52 + j] = ax * scale + __ldg(&gb[i * 52 + j]);
            if (j + 1 < NN)
                sS[i * 52 + j + 1] = ay * scale + __ldg(&gb[i * 52 + j + 1]);
        }
    }
    __syncthreads();

    // ---- softmax: one warp per row ----
    for (int i = w8; i < NN; i += 8) {
        float e0 = sS[i * 52 + lane];
        float e1 = (lane + 32 < NN) ? sS[i * 52 + lane + 32] : -1e30f;
        float mx = fmaxf(e0, e1);
#pragma unroll
        for (int o = 16; o; o >>= 1) mx = fmaxf(mx, __shfl_xor_sync(0xffffffffu, mx, o));
        e0 = __expf(e0 - mx);
        e1 = (lane + 32 < NN) ? __expf(e1 - mx) : 0.f;
        float sm = e0 + e1;
#pragma unroll
        for (int o = 16; o; o >>= 1) sm += __shfl_xor_sync(0xffffffffu, sm, o);
        float inv = 1.f / sm;
        sS[i * 52 + lane] = e0 * inv;
        if (lane + 32 < NN) sS[i * 52 + lane + 32] = e1 * inv;
    }
    __syncthreads();

    // ---- P @ V: 16 i-groups x 16 d-pairs ----
    const int dp = (t & 15) * 2;
    const int ig = t >> 4;
    float* outp = g_att + (size_t)w * NN * 256 + h * HD + dp;
    for (int i = ig; i < NN; i += 16) {
        float ax = 0.f, ay = 0.f;
#pragma unroll
        for (int jj = 0; jj < NN; jj++) {
            float p = sS[i * 52 + jj];                       // broadcast
            float2 v2 = *(const float2*)&vs[jj * HD + dp];   // conflict-free pairs
            ax += p * v2.x;
            ay += p * v2.y;
        }
        *(float2*)(outp + i * 256) = make_float2(ax, ay);
    }
}

// =====================================================================
extern "C" void kernel_launch(void* const* d_in, const int* in_sizes, int n_in,
                              void* d_out, int out_size) {
    const float* x     = (const float*)d_in[0];
    const float* qkvw  = (const float*)d_in[1];
    const float* qkvb  = (const float*)d_in[2];
    const float* projw = (const float*)d_in[3];
    const float* projb = (const float*)d_in[4];
    const float* tbl   = (const float*)d_in[5];
    const int*   ridx  = (const int*)d_in[6];
    float* out = (float*)d_out;

    (void)in_sizes; (void)n_in; (void)out_size;

    bias_kernel<<<32, 256>>>(tbl, ridx);
    gemm128<true><<<dim3(6, MTOT / 128), 256>>>(x, qkvw, qkvb, nullptr);
    attn_kernel<<<NWTOT * HEADS, 256>>>();
    gemm128<false><<<dim3(2, MTOT / 128), 256>>>(nullptr, projw, projb, out);
}

// round 13
// speedup vs baseline: 1.0592x; 1.0592x over previous
#include <cuda_runtime.h>
#include <cuda_bf16.h>
#include <mma.h>
#include <cstdint>

using namespace nvcuda;

// ---------------- problem constants ----------------
#define BATCH   32
#define HH      56
#define WW      56
#define CC      256
#define HEADS   8
#define HD      32
#define WIN     7
#define SHIFT   3
#define NN      49
#define NWIN    64
#define NWTOT   (BATCH * NWIN)      // 2048
#define MTOT    (NWTOT * NN)        // 100352
#define XN      (BATCH * HH * WW * CC)   // 25690112 elements

// ---------------- scratch (device globals; device-code refs only) ----------------
__device__ float g_qkv[(size_t)MTOT * 768];
__device__ float g_bias[4 * HEADS * NN * 52];

// bf16 hi/lo split copies (v = hi + lo to ~2^-18 rel)
__device__ __nv_bfloat16 g_xhi[XN],  g_xlo[XN];
__device__ __nv_bfloat16 g_ahi[XN],  g_alo[XN];   // attention output, split (written by attn)
__device__ __nv_bfloat16 g_wqhi[768 * 256], g_wqlo[768 * 256];
__device__ __nv_bfloat16 g_wphi[256 * 256], g_wplo[256 * 256];

// Map a flattened window-row index m -> element offset of the source pixel in x.
// roll(+3) inverts roll(-3): same map serves gather (QKV) and scatter (proj).
__device__ __forceinline__ int src_offset(int m) {
    int wq = m / NN;
    int n  = m - wq * NN;
    int b  = wq >> 6;
    int wi = wq & 63;
    int wh = wi >> 3, ww = wi & 7;
    int r = wh * WIN + n / WIN;
    int c = ww * WIN + n % WIN;
    int sh = r + SHIFT; if (sh >= HH) sh -= HH;
    int sw = c + SHIFT; if (sw >= WW) sw -= WW;
    return ((b * HH + sh) * WW + sw) * CC;
}

// =====================================================================
// Kernel 0: fused bias+mask table. 4 classes x 8 heads.
// =====================================================================
__global__ void bias_kernel(const float* __restrict__ tbl,
                            const int* __restrict__ relidx) {
    const int cls = blockIdx.x & 3;
    const int h   = blockIdx.x >> 2;
    for (int idx = threadIdx.x; idx < NN * NN; idx += blockDim.x) {
        int i = idx / NN, j = idx % NN;
        float b = tbl[relidx[idx] * HEADS + h];
        int rhi = (cls & 2) ? ((i / 7 < 4) ? 1 : 2) : 0;
        int rwi = (cls & 1) ? ((i % 7 < 4) ? 1 : 2) : 0;
        int rhj = (cls & 2) ? ((j / 7 < 4) ? 1 : 2) : 0;
        int rwj = (cls & 1) ? ((j % 7 < 4) ? 1 : 2) : 0;
        float msk = ((rhi * 3 + rwi) == (rhj * 3 + rwj)) ? 0.f : -100.f;
        g_bias[((cls * HEADS + h) * NN + i) * 52 + j] = b + msk;
    }
}

// =====================================================================
// Kernel 0b: fp32 -> bf16 hi/lo split. WHICH: 0=x, 1=qkvw, 2=projw
// =====================================================================
template<int WHICH>
__global__ void convsplit(const float* __restrict__ src, int n4) {
    __nv_bfloat16* hi;
    __nv_bfloat16* lo;
    if (WHICH == 0)      { hi = g_xhi;  lo = g_xlo;  }
    else if (WHICH == 1) { hi = g_wqhi; lo = g_wqlo; }
    else                 { hi = g_wphi; lo = g_wplo; }
    int i = blockIdx.x * blockDim.x + threadIdx.x;
    if (i < n4) {
        float4 v = ((const float4*)src)[i];
        __nv_bfloat16 h0 = __float2bfloat16(v.x);
        __nv_bfloat16 h1 = __float2bfloat16(v.y);
        __nv_bfloat16 h2 = __float2bfloat16(v.z);
        __nv_bfloat16 h3 = __float2bfloat16(v.w);
        __nv_bfloat16 l0 = __float2bfloat16(v.x - __bfloat162float(h0));
        __nv_bfloat16 l1 = __float2bfloat16(v.y - __bfloat162float(h1));
        __nv_bfloat16 l2 = __float2bfloat16(v.z - __bfloat162float(h2));
        __nv_bfloat16 l3 = __float2bfloat16(v.w - __bfloat162float(h3));
        ((__nv_bfloat162*)hi)[i * 2]     = __nv_bfloat162(h0, h1);
        ((__nv_bfloat162*)hi)[i * 2 + 1] = __nv_bfloat162(h2, h3);
        ((__nv_bfloat162*)lo)[i * 2]     = __nv_bfloat162(l0, l1);
        ((__nv_bfloat162*)lo)[i * 2 + 1] = __nv_bfloat162(l2, l3);
    }
}

// =====================================================================
// WMMA (HMMA) GEMM: 128x128 tile, 512 threads, K=256 in 8 blocks of 32,
// bf16 2-term split (Ahi*Bhi + Ahi*Blo + Alo*Bhi). Double-buffered SMEM,
// register prefetch, one __syncthreads per K-block.
// __launch_bounds__(512) with NO min-blocks clamp (the (512,2) clamp in R8
// forced 64 regs/thread and spilled the MMA loop; removing it was +490us).
// SMEM rows stride 40 elems (80 B): 80*m mod 128 covers 8 distinct 16B segs
// -> ldmatrix conflict-free.
//   QKV=true : A = x split (gathered via so[]), C = g_qkv (ldc=768)
//   QKV=false: A = attn-output split (linear),  C = OUT (scattered via so[])
// Measured (R9/R12 decomposition): pair ~917us vs fp32 pair 1082us.
// =====================================================================
#define GM_SMEM 81920

template<bool QKV>
__global__ __launch_bounds__(512) void wgemm(const float* __restrict__ bias,
                                             float* __restrict__ OUT) {
    extern __shared__ char dsm[];
    __shared__ float sbias[16][132];
    __shared__ int so[128];

    const int n0 = blockIdx.x * 128;
    const int m0 = blockIdx.y * 128;
    const int t  = threadIdx.x;
    const int w  = t >> 5;

    if (t < 128) so[t] = src_offset(m0 + t);
    for (int i = t; i < 16 * 128; i += 512) {
        int rr = i >> 7, cc = i & 127;
        sbias[rr][cc] = bias[n0 + cc];
    }
    __syncthreads();

    // ---- loader mapping: arr = t>>7 (0:Ahi 1:Alo 2:Bhi 3:Blo), row = t&127 ----
    const int arr  = t >> 7;
    const int lrow = t & 127;
    const __nv_bfloat16* gsrc;
    size_t gbase;
    if (arr == 0)      { gsrc = QKV ? g_xhi  : g_ahi;
                         gbase = QKV ? (size_t)so[lrow] : (size_t)(m0 + lrow) * 256; }
    else if (arr == 1) { gsrc = QKV ? g_xlo  : g_alo;
                         gbase = QKV ? (size_t)so[lrow] : (size_t)(m0 + lrow) * 256; }
    else if (arr == 2) { gsrc = QKV ? g_wqhi : g_wphi; gbase = (size_t)(n0 + lrow) * 256; }
    else               { gsrc = QKV ? g_wqlo : g_wplo; gbase = (size_t)(n0 + lrow) * 256; }
    const uint32_t soff = (uint32_t)arr * 10240u + (uint32_t)lrow * 80u;

    // ---- warp tile: wm in m (32 rows), wn in n (32 cols) ----
    const int wm = w & 3;
    const int wn = w >> 2;

    wmma::fragment<wmma::accumulator, 16, 16, 16, float> c[2][2];
#pragma unroll
    for (int i = 0; i < 2; i++)
#pragma unroll
        for (int j = 0; j < 2; j++)
            wmma::load_matrix_sync(c[i][j], &sbias[0][wn * 32 + j * 16], 132,
                                   wmma::mem_row_major);

    // ---- prologue: K-block 0 ----
    uint4 pf0, pf1, pf2, pf3;
    {
        const uint4* p = (const uint4*)(gsrc + gbase);
        pf0 = p[0]; pf1 = p[1]; pf2 = p[2]; pf3 = p[3];
        char* d = dsm + soff;
        *(uint4*)(d)      = pf0;
        *(uint4*)(d + 16) = pf1;
        *(uint4*)(d + 32) = pf2;
        *(uint4*)(d + 48) = pf3;
    }
    __syncthreads();

#pragma unroll 1
    for (int blk = 0; blk < 8; ++blk) {
        if (blk < 7) {
            const uint4* p = (const uint4*)(gsrc + gbase + (size_t)(blk + 1) * 32);
            pf0 = p[0]; pf1 = p[1]; pf2 = p[2]; pf3 = p[3];
        }

        char* bb = dsm + (blk & 1) * 40960;
#pragma unroll
        for (int ks = 0; ks < 32; ks += 16) {
            wmma::fragment<wmma::matrix_a, 16, 16, 16, __nv_bfloat16, wmma::row_major> ah[2], al[2];
#pragma unroll
            for (int i = 0; i < 2; i++) {
                const __nv_bfloat16* ap =
                    (const __nv_bfloat16*)(bb + (wm * 32 + i * 16) * 80) + ks;
                wmma::load_matrix_sync(ah[i], ap, 40);
                wmma::load_matrix_sync(al[i], ap + 5120, 40);   // +10240 B = 5120 elems
            }
#pragma unroll
            for (int j = 0; j < 2; j++) {
                wmma::fragment<wmma::matrix_b, 16, 16, 16, __nv_bfloat16, wmma::col_major> bh, bl;
                const __nv_bfloat16* bp =
                    (const __nv_bfloat16*)(bb + 20480 + (wn * 32 + j * 16) * 80) + ks;
                wmma::load_matrix_sync(bh, bp, 40);
                wmma::load_matrix_sync(bl, bp + 5120, 40);
#pragma unroll
                for (int i = 0; i < 2; i++) {
                    wmma::mma_sync(c[i][j], ah[i], bh, c[i][j]);
                    wmma::mma_sync(c[i][j], ah[i], bl, c[i][j]);
                    wmma::mma_sync(c[i][j], al[i], bh, c[i][j]);
                }
            }
        }

        if (blk < 7) {
            char* d = dsm + ((blk + 1) & 1) * 40960 + soff;
            *(uint4*)(d)      = pf0;
            *(uint4*)(d + 16) = pf1;
            *(uint4*)(d + 32) = pf2;
            *(uint4*)(d + 48) = pf3;
            __syncthreads();
        }
    }

    // ---- epilogue: stage via SMEM (scatter rows are non-affine) ----
    __syncthreads();
    float* co = (float*)dsm;
#pragma unroll
    for (int i = 0; i < 2; i++)
#pragma unroll
        for (int j = 0; j < 2; j++)
            wmma::store_matrix_sync(&co[(wm * 32 + i * 16) * 132 + wn * 32 + j * 16],
                                    c[i][j], 132, wmma::mem_row_major);
    __syncthreads();

    const int row = t >> 2;
    const int q   = t & 3;
    float* gdst;
    if (QKV) gdst = g_qkv + (size_t)(m0 + row) * 768 + n0 + q * 32;
    else     gdst = OUT + so[row] + n0 + q * 32;
    const float* cs = &co[row * 132 + q * 32];
#pragma unroll
    for (int jj = 0; jj < 8; ++jj)
        *(float4*)(gdst + jj * 4) = *(const float4*)(cs + jj * 4);
}

// =====================================================================
// Kernel 2: windowed attention (R4-proven shape). One block per (window, head).
// Epilogue writes the bf16 hi/lo split directly (feeds proj wgemm; kills the
// separate fp32 g_att buffer + convsplit pass).
// =====================================================================
__global__ __launch_bounds__(256) void attn_kernel() {
    __shared__ float qs[NN * HD];
    __shared__ float vs[NN * HD];
    __shared__ float kT[HD * 56];
    __shared__ float sS[NN * 52];

    const int w = blockIdx.x >> 3;
    const int h = blockIdx.x & 7;
    const int t = threadIdx.x;

    const int wi = w & 63;
    const int cls = (((wi >> 3) == 7) ? 2 : 0) | (((wi & 7) == 7) ? 1 : 0);
    const float* gb = g_bias + (size_t)((cls * HEADS + h) * NN) * 52;

    const float* base = g_qkv + (size_t)w * NN * 768 + h * HD;
    for (int idx = t; idx < NN * 8; idx += 256) {
        int n = idx >> 3, dq = idx & 7;
        const float4* p = (const float4*)(base + n * 768 + dq * 4);
        float4 q4 = p[0];
        float4 k4 = p[64];
        float4 v4 = p[128];
        *(float4*)&qs[n * HD + dq * 4] = q4;
        *(float4*)&vs[n * HD + dq * 4] = v4;
        kT[(dq * 4 + 0) * 56 + n] = k4.x;
        kT[(dq * 4 + 1) * 56 + n] = k4.y;
        kT[(dq * 4 + 2) * 56 + n] = k4.z;
        kT[(dq * 4 + 3) * 56 + n] = k4.w;
    }
    __syncthreads();

    // ---- scores: 4 row-groups x 64 j-lanes ----
    const int jg = t & 63, rgp = t >> 6;
    const float scale = 0.17677669529663687f;
    for (int i = rgp; i < NN; i += 4) {
        if (jg < NN) {
            float acc = 0.f;
#pragma unroll
            for (int kk = 0; kk < HD; kk++)
                acc += qs[i * HD + kk] * kT[kk * 56 + jg];
            sS[i * 52 + jg] = acc * scale + __ldg(&gb[i * 52 + jg]);
        }
    }
    __syncthreads();

    // ---- softmax: one warp per row ----
    const int wid = t >> 5, lane = t & 31;
    for (int i = wid; i < NN; i += 8) {
        float e0 = sS[i * 52 + lane];
        float e1 = (lane + 32 < NN) ? sS[i * 52 + lane + 32] : -1e30f;
        float mx = fmaxf(e0, e1);
#pragma unroll
        for (int o = 16; o; o >>= 1) mx = fmaxf(mx, __shfl_xor_sync(0xffffffffu, mx, o));
        e0 = __expf(e0 - mx);
        e1 = (lane + 32 < NN) ? __expf(e1 - mx) : 0.f;
        float sm = e0 + e1;
#pragma unroll
        for (int o = 16; o; o >>= 1) sm += __shfl_xor_sync(0xffffffffu, sm, o);
        float inv = 1.f / sm;
        sS[i * 52 + lane] = e0 * inv;
        if (lane + 32 < NN) sS[i * 52 + lane + 32] = e1 * inv;
    }
    __syncthreads();

    // ---- P @ V: 8 row-groups x 32 d-lanes; write bf16 hi/lo split ----
    const int d = t & 31, ig = t >> 5;
    const size_t obase = (size_t)w * NN * 256 + h * HD + d;
    for (int i = ig; i < NN; i += 8) {
        float acc = 0.f;
#pragma unroll
        for (int j = 0; j < NN; j++)
            acc += sS[i * 52 + j] * vs[j * HD + d];
        __nv_bfloat16 hi = __float2bfloat16(acc);
        __nv_bfloat16 lo = __float2bfloat16(acc - __bfloat162float(hi));
        g_ahi[obase + (size_t)i * 256] = hi;
        g_alo[obase + (size_t)i * 256] = lo;
    }
}

// =====================================================================
extern "C" void kernel_launch(void* const* d_in, const int* in_sizes, int n_in,
                              void* d_out, int out_size) {
    const float* x     = (const float*)d_in[0];
    const float* qkvw  = (const float*)d_in[1];
    const float* qkvb  = (const float*)d_in[2];
    const float* projw = (const float*)d_in[3];
    const float* projb = (const float*)d_in[4];
    const float* tbl   = (const float*)d_in[5];
    const int*   ridx  = (const int*)d_in[6];
    float* out = (float*)d_out;

    (void)in_sizes; (void)n_in; (void)out_size;

    cudaFuncSetAttribute(wgemm<true>,  cudaFuncAttributeMaxDynamicSharedMemorySize, GM_SMEM);
    cudaFuncSetAttribute(wgemm<false>, cudaFuncAttributeMaxDynamicSharedMemorySize, GM_SMEM);

    bias_kernel<<<32, 256>>>(tbl, ridx);
    convsplit<0><<<XN / 4 / 256, 256>>>(x, XN / 4);
    convsplit<1><<<(768 * 256) / 4 / 256, 256>>>(qkvw, (768 * 256) / 4);
    convsplit<2><<<(256 * 256) / 4 / 256, 256>>>(projw, (256 * 256) / 4);

    wgemm<true><<<dim3(6, MTOT / 128), 512, GM_SMEM>>>(qkvb, nullptr);
    attn_kernel<<<NWTOT * HEADS, 256>>>();
    wgemm<false><<<dim3(2, MTOT / 128), 512, GM_SMEM>>>(projb, out);
}

// round 14
// speedup vs baseline: 1.0655x; 1.0060x over previous
#include <cuda_runtime.h>
#include <cuda_bf16.h>
#include <mma.h>
#include <cstdint>

using namespace nvcuda;

// ---------------- problem constants ----------------
#define BATCH   32
#define HH      56
#define WW      56
#define CC      256
#define HEADS   8
#define HD      32
#define WIN     7
#define SHIFT   3
#define NN      49
#define NWIN    64
#define NWTOT   (BATCH * NWIN)      // 2048
#define MTOT    (NWTOT * NN)        // 100352
#define XN      (BATCH * HH * WW * CC)   // 25690112 elements

// ---------------- scratch (device globals; device-code refs only) ----------------
__device__ float g_qkv[(size_t)MTOT * 768];
__device__ float g_bias[4 * HEADS * NN * 52];

// bf16 hi/lo split copies (v = hi + lo to ~2^-18 rel)
__device__ __nv_bfloat16 g_ahi[XN],  g_alo[XN];   // attention output, split (written by attn)
__device__ __nv_bfloat16 g_wqhi[768 * 256], g_wqlo[768 * 256];
__device__ __nv_bfloat16 g_wphi[256 * 256], g_wplo[256 * 256];

__device__ __forceinline__ uint32_t pack_bf2(float a, float b) {
    __nv_bfloat162 t(__float2bfloat16(a), __float2bfloat16(b));
    return *(uint32_t*)&t;
}

// Map a flattened window-row index m -> element offset of the source pixel in x.
// roll(+3) inverts roll(-3): same map serves gather (QKV) and scatter (proj).
__device__ __forceinline__ int src_offset(int m) {
    int wq = m / NN;
    int n  = m - wq * NN;
    int b  = wq >> 6;
    int wi = wq & 63;
    int wh = wi >> 3, ww = wi & 7;
    int r = wh * WIN + n / WIN;
    int c = ww * WIN + n % WIN;
    int sh = r + SHIFT; if (sh >= HH) sh -= HH;
    int sw = c + SHIFT; if (sw >= WW) sw -= WW;
    return ((b * HH + sh) * WW + sw) * CC;
}

// =====================================================================
// Kernel 0: fused bias+mask table. 4 classes x 8 heads.
// =====================================================================
__global__ void bias_kernel(const float* __restrict__ tbl,
                            const int* __restrict__ relidx) {
    const int cls = blockIdx.x & 3;
    const int h   = blockIdx.x >> 2;
    for (int idx = threadIdx.x; idx < NN * NN; idx += blockDim.x) {
        int i = idx / NN, j = idx % NN;
        float b = tbl[relidx[idx] * HEADS + h];
        int rhi = (cls & 2) ? ((i / 7 < 4) ? 1 : 2) : 0;
        int rwi = (cls & 1) ? ((i % 7 < 4) ? 1 : 2) : 0;
        int rhj = (cls & 2) ? ((j / 7 < 4) ? 1 : 2) : 0;
        int rwj = (cls & 1) ? ((j % 7 < 4) ? 1 : 2) : 0;
        float msk = ((rhi * 3 + rwi) == (rhj * 3 + rwj)) ? 0.f : -100.f;
        g_bias[((cls * HEADS + h) * NN + i) * 52 + j] = b + msk;
    }
}

// =====================================================================
// Kernel 0b: fp32 -> bf16 hi/lo split for WEIGHTS only. WHICH: 1=qkvw, 2=projw
// (x split is fused into wgemm<true>'s loader; attn writes its own split.)
// =====================================================================
template<int WHICH>
__global__ void convsplit(const float* __restrict__ src, int n4) {
    __nv_bfloat16* hi;
    __nv_bfloat16* lo;
    if (WHICH == 1) { hi = g_wqhi; lo = g_wqlo; }
    else            { hi = g_wphi; lo = g_wplo; }
    int i = blockIdx.x * blockDim.x + threadIdx.x;
    if (i < n4) {
        float4 v = ((const float4*)src)[i];
        __nv_bfloat16 h0 = __float2bfloat16(v.x);
        __nv_bfloat16 h1 = __float2bfloat16(v.y);
        __nv_bfloat16 h2 = __float2bfloat16(v.z);
        __nv_bfloat16 h3 = __float2bfloat16(v.w);
        __nv_bfloat16 l0 = __float2bfloat16(v.x - __bfloat162float(h0));
        __nv_bfloat16 l1 = __float2bfloat16(v.y - __bfloat162float(h1));
        __nv_bfloat16 l2 = __float2bfloat16(v.z - __bfloat162float(h2));
        __nv_bfloat16 l3 = __float2bfloat16(v.w - __bfloat162float(h3));
        ((__nv_bfloat162*)hi)[i * 2]     = __nv_bfloat162(h0, h1);
        ((__nv_bfloat162*)hi)[i * 2 + 1] = __nv_bfloat162(h2, h3);
        ((__nv_bfloat162*)lo)[i * 2]     = __nv_bfloat162(l0, l1);
        ((__nv_bfloat162*)lo)[i * 2 + 1] = __nv_bfloat162(l2, l3);
    }
}

// =====================================================================
// WMMA (HMMA) GEMM: 128x128 tile, 512 threads, K=256 in 8 blocks of 32,
// bf16 2-term split (Ahi*Bhi + Ahi*Blo + Alo*Bhi). Double-buffered SMEM,
// register prefetch (4x uint4 per thread — identical footprint both paths),
// one __syncthreads per K-block. __launch_bounds__(512), NO min-blocks clamp.
// SMEM rows stride 40 elems (80 B). Arrays per buffer:
//   Ahi @0, Alo @10240, Bhi @20480, Blo @30720; buffer 1 at +40960.
//
//   QKV=true : A = fp32 x, gathered via so[], CONVERTED TO HI/LO IN THE
//              LOADER (threads 0-255: row=t>>1, half=t&1 -> 16 fp32 = 64 B
//              prefetch -> 32 B Ahi + 32 B Alo at STS time).
//              B = g_wq{hi,lo} (threads 256-511). C = g_qkv (ldc=768).
//   QKV=false: original 4-array loader (g_a{hi,lo}, g_wp{hi,lo});
//              C = OUT (scattered via so[]).
// =====================================================================
#define GM_SMEM 81920

template<bool QKV>
__global__ __launch_bounds__(512) void wgemm(const float* __restrict__ X,
                                             const float* __restrict__ bias,
                                             float* __restrict__ OUT) {
    extern __shared__ char dsm[];
    __shared__ float sbias[16][132];
    __shared__ int so[128];

    const int n0 = blockIdx.x * 128;
    const int m0 = blockIdx.y * 128;
    const int t  = threadIdx.x;
    const int w  = t >> 5;

    if (t < 128) so[t] = src_offset(m0 + t);
    for (int i = t; i < 16 * 128; i += 512) {
        int rr = i >> 7, cc = i & 127;
        sbias[rr][cc] = bias[n0 + cc];
    }
    __syncthreads();

    // ---- loader mapping ----
    // QKV path:  t<256: A fp32 (row=t>>1, kh=t&1);  t>=256: B bf16 (arr=(t>>7)&1)
    // proj path: arr = t>>7 (0:Ahi 1:Alo 2:Bhi 3:Blo), lrow = t&127
    const float* axp = nullptr;        // QKV A fp32 source
    const __nv_bfloat16* gsrc = nullptr;
    size_t gbase = 0;
    uint32_t soff = 0;                 // smem byte offset within buffer
    if (QKV) {
        if (t < 256) {
            const int row = t >> 1;
            const int kh  = t & 1;
            axp  = X + so[row] + kh * 16;
            soff = (uint32_t)row * 80u + (uint32_t)kh * 32u;   // Ahi base
        } else {
            const int arr  = (t >> 7) & 1;     // 0:Bhi 1:Blo
            const int lrow = t & 127;
            gsrc  = arr ? g_wqlo : g_wqhi;
            gbase = (size_t)(n0 + lrow) * 256;
            soff  = 20480u + (uint32_t)arr * 10240u + (uint32_t)lrow * 80u;
        }
    } else {
        const int arr  = t >> 7;
        const int lrow = t & 127;
        if (arr == 0)      { gsrc = g_ahi;  gbase = (size_t)(m0 + lrow) * 256; }
        else if (arr == 1) { gsrc = g_alo;  gbase = (size_t)(m0 + lrow) * 256; }
        else if (arr == 2) { gsrc = g_wphi; gbase = (size_t)(n0 + lrow) * 256; }
        else               { gsrc = g_wplo; gbase = (size_t)(n0 + lrow) * 256; }
        soff = (uint32_t)(t >> 7) * 10240u + (uint32_t)(t & 127) * 80u;
    }

    // ---- warp tile: wm in m (32 rows), wn in n (32 cols) ----
    const int wm = w & 3;
    const int wn = w >> 2;

    wmma::fragment<wmma::accumulator, 16, 16, 16, float> c[2][2];
#pragma unroll
    for (int i = 0; i < 2; i++)
#pragma unroll
        for (int j = 0; j < 2; j++)
            wmma::load_matrix_sync(c[i][j], &sbias[0][wn * 32 + j * 16], 132,
                                   wmma::mem_row_major);

    // ---- store helper: A-convert path writes hi+lo, plain path writes raw ----
    uint4 pf0, pf1, pf2, pf3;
    auto stage = [&](char* bufbase) {
        if (QKV && t < 256) {
            // pf0..3 hold 16 fp32 of x -> split to 16 bf16 hi + 16 bf16 lo
            float f[16] = {
                __uint_as_float(pf0.x), __uint_as_float(pf0.y),
                __uint_as_float(pf0.z), __uint_as_float(pf0.w),
                __uint_as_float(pf1.x), __uint_as_float(pf1.y),
                __uint_as_float(pf1.z), __uint_as_float(pf1.w),
                __uint_as_float(pf2.x), __uint_as_float(pf2.y),
                __uint_as_float(pf2.z), __uint_as_float(pf2.w),
                __uint_as_float(pf3.x), __uint_as_float(pf3.y),
                __uint_as_float(pf3.z), __uint_as_float(pf3.w)
            };
            uint32_t hh[8], ll[8];
#pragma unroll
            for (int j = 0; j < 8; j++) {
                float a = f[2 * j], b = f[2 * j + 1];
                __nv_bfloat16 ha = __float2bfloat16(a);
                __nv_bfloat16 hb = __float2bfloat16(b);
                hh[j] = pack_bf2(a, b);     // hi pair (same rounding)
                ll[j] = pack_bf2(a - __bfloat162float(ha), b - __bfloat162float(hb));
            }
            char* d = bufbase + soff;
            *(uint4*)(d)              = make_uint4(hh[0], hh[1], hh[2], hh[3]);
            *(uint4*)(d + 16)         = make_uint4(hh[4], hh[5], hh[6], hh[7]);
            *(uint4*)(d + 10240)      = make_uint4(ll[0], ll[1], ll[2], ll[3]);
            *(uint4*)(d + 10240 + 16) = make_uint4(ll[4], ll[5], ll[6], ll[7]);
        } else {
            char* d = bufbase + soff;
            *(uint4*)(d)      = pf0;
            *(uint4*)(d + 16) = pf1;
            *(uint4*)(d + 32) = pf2;
            *(uint4*)(d + 48) = pf3;
        }
    };
    auto prefetch = [&](int blk) {
        if (QKV && t < 256) {
            const uint4* p = (const uint4*)(axp + (size_t)blk * 32);   // 16 fp32 = 64 B
            pf0 = p[0]; pf1 = p[1]; pf2 = p[2]; pf3 = p[3];
        } else {
            const uint4* p = (const uint4*)(gsrc + gbase + (size_t)blk * 32);  // 32 bf16
            pf0 = p[0]; pf1 = p[1]; pf2 = p[2]; pf3 = p[3];
        }
    };

    // ---- prologue: K-block 0 ----
    prefetch(0);
    stage(dsm);
    __syncthreads();

#pragma unroll 1
    for (int blk = 0; blk < 8; ++blk) {
        if (blk < 7) prefetch(blk + 1);

        char* bb = dsm + (blk & 1) * 40960;
#pragma unroll
        for (int ks = 0; ks < 32; ks += 16) {
            wmma::fragment<wmma::matrix_a, 16, 16, 16, __nv_bfloat16, wmma::row_major> ah[2], al[2];
#pragma unroll
            for (int i = 0; i < 2; i++) {
                const __nv_bfloat16* ap =
                    (const __nv_bfloat16*)(bb + (wm * 32 + i * 16) * 80) + ks;
                wmma::load_matrix_sync(ah[i], ap, 40);
                wmma::load_matrix_sync(al[i], ap + 5120, 40);   // +10240 B = 5120 elems
            }
#pragma unroll
            for (int j = 0; j < 2; j++) {
                wmma::fragment<wmma::matrix_b, 16, 16, 16, __nv_bfloat16, wmma::col_major> bh, bl;
                const __nv_bfloat16* bp =
                    (const __nv_bfloat16*)(bb + 20480 + (wn * 32 + j * 16) * 80) + ks;
                wmma::load_matrix_sync(bh, bp, 40);
                wmma::load_matrix_sync(bl, bp + 5120, 40);
#pragma unroll
                for (int i = 0; i < 2; i++) {
                    wmma::mma_sync(c[i][j], ah[i], bh, c[i][j]);
                    wmma::mma_sync(c[i][j], ah[i], bl, c[i][j]);
                    wmma::mma_sync(c[i][j], al[i], bh, c[i][j]);
                }
            }
        }

        if (blk < 7) {
            stage(dsm + ((blk + 1) & 1) * 40960);
            __syncthreads();
        }
    }

    // ---- epilogue: stage via SMEM (scatter rows are non-affine) ----
    __syncthreads();
    float* co = (float*)dsm;
#pragma unroll
    for (int i = 0; i < 2; i++)
#pragma unroll
        for (int j = 0; j < 2; j++)
            wmma::store_matrix_sync(&co[(wm * 32 + i * 16) * 132 + wn * 32 + j * 16],
                                    c[i][j], 132, wmma::mem_row_major);
    __syncthreads();

    const int row = t >> 2;
    const int q   = t & 3;
    float* gdst;
    if (QKV) gdst = g_qkv + (size_t)(m0 + row) * 768 + n0 + q * 32;
    else     gdst = OUT + so[row] + n0 + q * 32;
    const float* cs = &co[row * 132 + q * 32];
#pragma unroll
    for (int jj = 0; jj < 8; ++jj)
        *(float4*)(gdst + jj * 4) = *(const float4*)(cs + jj * 4);
}

// =====================================================================
// Kernel 2: windowed attention (R4-proven shape). One block per (window, head).
// Epilogue writes the bf16 hi/lo split directly (feeds proj wgemm).
// =====================================================================
__global__ __launch_bounds__(256) void attn_kernel() {
    __shared__ float qs[NN * HD];
    __shared__ float vs[NN * HD];
    __shared__ float kT[HD * 56];
    __shared__ float sS[NN * 52];

    const int w = blockIdx.x >> 3;
    const int h = blockIdx.x & 7;
    const int t = threadIdx.x;

    const int wi = w & 63;
    const int cls = (((wi >> 3) == 7) ? 2 : 0) | (((wi & 7) == 7) ? 1 : 0);
    const float* gb = g_bias + (size_t)((cls * HEADS + h) * NN) * 52;

    const float* base = g_qkv + (size_t)w * NN * 768 + h * HD;
    for (int idx = t; idx < NN * 8; idx += 256) {
        int n = idx >> 3, dq = idx & 7;
        const float4* p = (const float4*)(base + n * 768 + dq * 4);
        float4 q4 = p[0];
        float4 k4 = p[64];
        float4 v4 = p[128];
        *(float4*)&qs[n * HD + dq * 4] = q4;
        *(float4*)&vs[n * HD + dq * 4] = v4;
        kT[(dq * 4 + 0) * 56 + n] = k4.x;
        kT[(dq * 4 + 1) * 56 + n] = k4.y;
        kT[(dq * 4 + 2) * 56 + n] = k4.z;
        kT[(dq * 4 + 3) * 56 + n] = k4.w;
    }
    __syncthreads();

    // ---- scores: 4 row-groups x 64 j-lanes ----
    const int jg = t & 63, rgp = t >> 6;
    const float scale = 0.17677669529663687f;
    for (int i = rgp; i < NN; i += 4) {
        if (jg < NN) {
            float acc = 0.f;
#pragma unroll
            for (int kk = 0; kk < HD; kk++)
                acc += qs[i * HD + kk] * kT[kk * 56 + jg];
            sS[i * 52 + jg] = acc * scale + __ldg(&gb[i * 52 + jg]);
        }
    }
    __syncthreads();

    // ---- softmax: one warp per row ----
    const int wid = t >> 5, lane = t & 31;
    for (int i = wid; i < NN; i += 8) {
        float e0 = sS[i * 52 + lane];
        float e1 = (lane + 32 < NN) ? sS[i * 52 + lane + 32] : -1e30f;
        float mx = fmaxf(e0, e1);
#pragma unroll
        for (int o = 16; o; o >>= 1) mx = fmaxf(mx, __shfl_xor_sync(0xffffffffu, mx, o));
        e0 = __expf(e0 - mx);
        e1 = (lane + 32 < NN) ? __expf(e1 - mx) : 0.f;
        float sm = e0 + e1;
#pragma unroll
        for (int o = 16; o; o >>= 1) sm += __shfl_xor_sync(0xffffffffu, sm, o);
        float inv = 1.f / sm;
        sS[i * 52 + lane] = e0 * inv;
        if (lane + 32 < NN) sS[i * 52 + lane + 32] = e1 * inv;
    }
    __syncthreads();

    // ---- P @ V: 8 row-groups x 32 d-lanes; write bf16 hi/lo split ----
    const int d = t & 31, ig = t >> 5;
    const size_t obase = (size_t)w * NN * 256 + h * HD + d;
    for (int i = ig; i < NN; i += 8) {
        float acc = 0.f;
#pragma unroll
        for (int j = 0; j < NN; j++)
            acc += sS[i * 52 + j] * vs[j * HD + d];
        __nv_bfloat16 hi = __float2bfloat16(acc);
        __nv_bfloat16 lo = __float2bfloat16(acc - __bfloat162float(hi));
        g_ahi[obase + (size_t)i * 256] = hi;
        g_alo[obase + (size_t)i * 256] = lo;
    }
}

// =====================================================================
extern "C" void kernel_launch(void* const* d_in, const int* in_sizes, int n_in,
                              void* d_out, int out_size) {
    const float* x     = (const float*)d_in[0];
    const float* qkvw  = (const float*)d_in[1];
    const float* qkvb  = (const float*)d_in[2];
    const float* projw = (const float*)d_in[3];
    const float* projb = (const float*)d_in[4];
    const float* tbl   = (const float*)d_in[5];
    const int*   ridx  = (const int*)d_in[6];
    float* out = (float*)d_out;

    (void)in_sizes; (void)n_in; (void)out_size;

    cudaFuncSetAttribute(wgemm<true>,  cudaFuncAttributeMaxDynamicSharedMemorySize, GM_SMEM);
    cudaFuncSetAttribute(wgemm<false>, cudaFuncAttributeMaxDynamicSharedMemorySize, GM_SMEM);

    bias_kernel<<<32, 256>>>(tbl, ridx);
    convsplit<1><<<(768 * 256) / 4 / 256, 256>>>(qkvw, (768 * 256) / 4);
    convsplit<2><<<(256 * 256) / 4 / 256, 256>>>(projw, (256 * 256) / 4);

    wgemm<true><<<dim3(6, MTOT / 128), 512, GM_SMEM>>>(x, qkvb, nullptr);
    attn_kernel<<<NWTOT * HEADS, 256>>>();
    wgemm<false><<<dim3(2, MTOT / 128), 512, GM_SMEM>>>(nullptr, projb, out);
}

// round 15
// speedup vs baseline: 1.2935x; 1.2139x over previous
#include <cuda_runtime.h>
#include <cuda_bf16.h>
#include <mma.h>
#include <cstdint>

using namespace nvcuda;

// ---------------- problem constants ----------------
#define BATCH   32
#define HH      56
#define WW      56
#define CC      256
#define HEADS   8
#define HD      32
#define WIN     7
#define SHIFT   3
#define NN      49
#define NWIN    64
#define NWTOT   (BATCH * NWIN)      // 2048
#define MTOT    (NWTOT * NN)        // 100352
#define XN      (BATCH * HH * WW * CC)   // 25690112 elements

// ---------------- scratch (device globals; device-code refs only) ----------------
__device__ float g_qkv[(size_t)MTOT * 768];
__device__ float g_bias[4 * HEADS * NN * 52];

// bf16 hi/lo split copies (v = hi + lo to ~2^-18 rel)
__device__ __nv_bfloat16 g_xhi[XN],  g_xlo[XN];
__device__ __nv_bfloat16 g_ahi[XN],  g_alo[XN];   // attention output (written by attn)
__device__ __nv_bfloat16 g_wqhi[768 * 256], g_wqlo[768 * 256];
__device__ __nv_bfloat16 g_wphi[256 * 256], g_wplo[256 * 256];

// ---------------- cp.async helpers ----------------
#define CP16(d, s) \
    asm volatile("cp.async.cg.shared.global [%0], [%1], 16;" :: "r"(d), "l"(s))
#define CP_COMMIT() asm volatile("cp.async.commit_group;" ::: "memory")
#define CP_WAIT0()  asm volatile("cp.async.wait_group 0;" ::: "memory")

// Map a flattened window-row index m -> element offset of the source pixel in x.
// roll(+3) inverts roll(-3): same map serves gather (QKV) and scatter (proj).
__device__ __forceinline__ int src_offset(int m) {
    int wq = m / NN;
    int n  = m - wq * NN;
    int b  = wq >> 6;
    int wi = wq & 63;
    int wh = wi >> 3, ww = wi & 7;
    int r = wh * WIN + n / WIN;
    int c = ww * WIN + n % WIN;
    int sh = r + SHIFT; if (sh >= HH) sh -= HH;
    int sw = c + SHIFT; if (sw >= WW) sw -= WW;
    return ((b * HH + sh) * WW + sw) * CC;
}

// =====================================================================
// Kernel 0: fused bias+mask table. 4 classes x 8 heads.
// =====================================================================
__global__ void bias_kernel(const float* __restrict__ tbl,
                            const int* __restrict__ relidx) {
    const int cls = blockIdx.x & 3;
    const int h   = blockIdx.x >> 2;
    for (int idx = threadIdx.x; idx < NN * NN; idx += blockDim.x) {
        int i = idx / NN, j = idx % NN;
        float b = tbl[relidx[idx] * HEADS + h];
        int rhi = (cls & 2) ? ((i / 7 < 4) ? 1 : 2) : 0;
        int rwi = (cls & 1) ? ((i % 7 < 4) ? 1 : 2) : 0;
        int rhj = (cls & 2) ? ((j / 7 < 4) ? 1 : 2) : 0;
        int rwj = (cls & 1) ? ((j % 7 < 4) ? 1 : 2) : 0;
        float msk = ((rhi * 3 + rwi) == (rhj * 3 + rwj)) ? 0.f : -100.f;
        g_bias[((cls * HEADS + h) * NN + i) * 52 + j] = b + msk;
    }
}

// =====================================================================
// Kernel 0b: fp32 -> bf16 hi/lo split. WHICH: 0=x, 1=qkvw, 2=projw
// =====================================================================
template<int WHICH>
__global__ void convsplit(const float* __restrict__ src, int n4) {
    __nv_bfloat16* hi;
    __nv_bfloat16* lo;
    if (WHICH == 0)      { hi = g_xhi;  lo = g_xlo;  }
    else if (WHICH == 1) { hi = g_wqhi; lo = g_wqlo; }
    else                 { hi = g_wphi; lo = g_wplo; }
    int i = blockIdx.x * blockDim.x + threadIdx.x;
    if (i < n4) {
        float4 v = ((const float4*)src)[i];
        __nv_bfloat16 h0 = __float2bfloat16(v.x);
        __nv_bfloat16 h1 = __float2bfloat16(v.y);
        __nv_bfloat16 h2 = __float2bfloat16(v.z);
        __nv_bfloat16 h3 = __float2bfloat16(v.w);
        __nv_bfloat16 l0 = __float2bfloat16(v.x - __bfloat162float(h0));
        __nv_bfloat16 l1 = __float2bfloat16(v.y - __bfloat162float(h1));
        __nv_bfloat16 l2 = __float2bfloat16(v.z - __bfloat162float(h2));
        __nv_bfloat16 l3 = __float2bfloat16(v.w - __bfloat162float(h3));
        ((__nv_bfloat162*)hi)[i * 2]     = __nv_bfloat162(h0, h1);
        ((__nv_bfloat162*)hi)[i * 2 + 1] = __nv_bfloat162(h2, h3);
        ((__nv_bfloat162*)lo)[i * 2]     = __nv_bfloat162(l0, l1);
        ((__nv_bfloat162*)lo)[i * 2 + 1] = __nv_bfloat162(l2, l3);
    }
}

// =====================================================================
// WMMA (HMMA) GEMM v2: 128x128 tile, 256 threads (8 warps), warp tile
// 64x32 (2m x 4n layout, c[4][2]) -> 0.5 fragment-loads per MMA (was 0.67).
// All staging via cp.async (no register prefetch, no STS in issue stream),
// double-buffered, one __syncthreads per K-block.
// __launch_bounds__(256, 2): 128-reg cap (est. usage ~112, no spill) +
// 2 CTAs/SM (2 x ~82KB smem <= 228KB) so sync bubbles overlap across CTAs.
// SMEM rows stride 40 elems (80 B): conflict-free LDSM. Per-buffer arrays:
//   Ahi @0, Alo @10240, Bhi @20480, Blo @30720; buffer 1 at +40960.
// Bias added in epilogue (no sbias tile).
//   QKV=true : A = g_x{hi,lo} gathered via so[], C = g_qkv (ldc=768)
//   QKV=false: A = g_a{hi,lo} linear,            C = OUT (scattered via so[])
// =====================================================================
#define GM_SMEM 81920

template<bool QKV>
__global__ __launch_bounds__(256, 2) void wgemm(const float* __restrict__ bias,
                                                float* __restrict__ OUT) {
    extern __shared__ char dsm[];
    __shared__ int so[128];

    const int n0 = blockIdx.x * 128;
    const int m0 = blockIdx.y * 128;
    const int t  = threadIdx.x;
    const int w  = t >> 5;

    if (t < 128) so[t] = src_offset(m0 + t);
    __syncthreads();

    // ---- loader mapping: row = t>>1 (0..127), kh = t&1 (16-elem half) ----
    const int row = t >> 1;
    const int kh  = t & 1;
    const __nv_bfloat16 *Ahi, *Alo, *Bhi, *Blo;
    size_t abase;
    if (QKV) { Ahi = g_xhi; Alo = g_xlo; Bhi = g_wqhi; Blo = g_wqlo;
               abase = (size_t)so[row]; }
    else     { Ahi = g_ahi; Alo = g_alo; Bhi = g_wphi; Blo = g_wplo;
               abase = (size_t)(m0 + row) * 256; }
    const size_t bbase = (size_t)(n0 + row) * 256;
    const uint32_t dsmem = (uint32_t)__cvta_generic_to_shared(dsm);
    const uint32_t arow  = (uint32_t)row * 80u + (uint32_t)kh * 32u;

    // issue one K-block's 8x 16B cp.async for this thread into buffer at bufoff
    auto issue = [&](int blk, uint32_t bufoff) {
        const size_t go = (size_t)blk * 32 + kh * 16;
        const uint32_t d = dsmem + bufoff + arow;
        CP16(d,              Ahi + abase + go);
        CP16(d + 16,         Ahi + abase + go + 8);
        CP16(d + 10240,      Alo + abase + go);
        CP16(d + 10240 + 16, Alo + abase + go + 8);
        CP16(d + 20480,      Bhi + bbase + go);
        CP16(d + 20480 + 16, Bhi + bbase + go + 8);
        CP16(d + 30720,      Blo + bbase + go);
        CP16(d + 30720 + 16, Blo + bbase + go + 8);
    };

    // ---- warp tile: wm = w&1 (64 m-rows), wn = w>>1 (32 n-cols) ----
    const int wm = w & 1;
    const int wn = w >> 1;

    wmma::fragment<wmma::accumulator, 16, 16, 16, float> c[4][2];
#pragma unroll
    for (int i = 0; i < 4; i++)
#pragma unroll
        for (int j = 0; j < 2; j++) wmma::fill_fragment(c[i][j], 0.f);

    // ---- prologue ----
    issue(0, 0);
    CP_COMMIT();

#pragma unroll 1
    for (int blk = 0; blk < 8; ++blk) {
        CP_WAIT0();
        __syncthreads();
        if (blk < 7) {                        // target buffer last read at blk-1
            issue(blk + 1, (uint32_t)((blk + 1) & 1) * 40960u);
            CP_COMMIT();
        }

        char* bb = dsm + (blk & 1) * 40960;
#pragma unroll
        for (int ks = 0; ks < 32; ks += 16) {
            wmma::fragment<wmma::matrix_a, 16, 16, 16, __nv_bfloat16, wmma::row_major> ah[4], al[4];
#pragma unroll
            for (int i = 0; i < 4; i++) {
                const __nv_bfloat16* ap =
                    (const __nv_bfloat16*)(bb + (wm * 64 + i * 16) * 80) + ks;
                wmma::load_matrix_sync(ah[i], ap, 40);
                wmma::load_matrix_sync(al[i], ap + 5120, 40);   // +10240 B
            }
#pragma unroll
            for (int j = 0; j < 2; j++) {
                wmma::fragment<wmma::matrix_b, 16, 16, 16, __nv_bfloat16, wmma::col_major> bh, bl;
                const __nv_bfloat16* bp =
                    (const __nv_bfloat16*)(bb + 20480 + (wn * 32 + j * 16) * 80) + ks;
                wmma::load_matrix_sync(bh, bp, 40);
                wmma::load_matrix_sync(bl, bp + 5120, 40);
#pragma unroll
                for (int i = 0; i < 4; i++) {
                    wmma::mma_sync(c[i][j], ah[i], bh, c[i][j]);
                    wmma::mma_sync(c[i][j], ah[i], bl, c[i][j]);
                    wmma::mma_sync(c[i][j], al[i], bh, c[i][j]);
                }
            }
        }
    }

    // ---- epilogue: stage via SMEM (scatter rows are non-affine), add bias ----
    __syncthreads();
    float* co = (float*)dsm;                       // 128x132 f32 = 67584 B
#pragma unroll
    for (int i = 0; i < 4; i++)
#pragma unroll
        for (int j = 0; j < 2; j++)
            wmma::store_matrix_sync(&co[(wm * 64 + i * 16) * 132 + wn * 32 + j * 16],
                                    c[i][j], 132, wmma::mem_row_major);
    __syncthreads();

    // row = t>>1 writes 64 cols at half kh
    const float* cs = &co[row * 132 + kh * 64];
    float* gdst;
    if (QKV) gdst = g_qkv + (size_t)(m0 + row) * 768 + n0 + kh * 64;
    else     gdst = OUT + so[row] + n0 + kh * 64;
#pragma unroll
    for (int jj = 0; jj < 16; ++jj) {
        float4 bv = *(const float4*)(bias + n0 + kh * 64 + jj * 4);
        float4 o  = *(const float4*)(cs + jj * 4);
        o.x += bv.x; o.y += bv.y; o.z += bv.z; o.w += bv.w;
        *(float4*)(gdst + jj * 4) = o;
    }
}

// =====================================================================
// Kernel 2: windowed attention (R4-proven shape). One block per (window, head).
// Epilogue writes the bf16 hi/lo split directly (feeds proj wgemm).
// =====================================================================
__global__ __launch_bounds__(256) void attn_kernel() {
    __shared__ float qs[NN * HD];
    __shared__ float vs[NN * HD];
    __shared__ float kT[HD * 56];
    __shared__ float sS[NN * 52];

    const int w = blockIdx.x >> 3;
    const int h = blockIdx.x & 7;
    const int t = threadIdx.x;

    const int wi = w & 63;
    const int cls = (((wi >> 3) == 7) ? 2 : 0) | (((wi & 7) == 7) ? 1 : 0);
    const float* gb = g_bias + (size_t)((cls * HEADS + h) * NN) * 52;

    const float* base = g_qkv + (size_t)w * NN * 768 + h * HD;
    for (int idx = t; idx < NN * 8; idx += 256) {
        int n = idx >> 3, dq = idx & 7;
        const float4* p = (const float4*)(base + n * 768 + dq * 4);
        float4 q4 = p[0];
        float4 k4 = p[64];
        float4 v4 = p[128];
        *(float4*)&qs[n * HD + dq * 4] = q4;
        *(float4*)&vs[n * HD + dq * 4] = v4;
        kT[(dq * 4 + 0) * 56 + n] = k4.x;
        kT[(dq * 4 + 1) * 56 + n] = k4.y;
        kT[(dq * 4 + 2) * 56 + n] = k4.z;
        kT[(dq * 4 + 3) * 56 + n] = k4.w;
    }
    __syncthreads();

    // ---- scores: 4 row-groups x 64 j-lanes ----
    const int jg = t & 63, rgp = t >> 6;
    const float scale = 0.17677669529663687f;
    for (int i = rgp; i < NN; i += 4) {
        if (jg < NN) {
            float acc = 0.f;
#pragma unroll
            for (int kk = 0; kk < HD; kk++)
                acc += qs[i * HD + kk] * kT[kk * 56 + jg];
            sS[i * 52 + jg] = acc * scale + __ldg(&gb[i * 52 + jg]);
        }
    }
    __syncthreads();

    // ---- softmax: one warp per row ----
    const int wid = t >> 5, lane = t & 31;
    for (int i = wid; i < NN; i += 8) {
        float e0 = sS[i * 52 + lane];
        float e1 = (lane + 32 < NN) ? sS[i * 52 + lane + 32] : -1e30f;
        float mx = fmaxf(e0, e1);
#pragma unroll
        for (int o = 16; o; o >>= 1) mx = fmaxf(mx, __shfl_xor_sync(0xffffffffu, mx, o));
        e0 = __expf(e0 - mx);
        e1 = (lane + 32 < NN) ? __expf(e1 - mx) : 0.f;
        float sm = e0 + e1;
#pragma unroll
        for (int o = 16; o; o >>= 1) sm += __shfl_xor_sync(0xffffffffu, sm, o);
        float inv = 1.f / sm;
        sS[i * 52 + lane] = e0 * inv;
        if (lane + 32 < NN) sS[i * 52 + lane + 32] = e1 * inv;
    }
    __syncthreads();

    // ---- P @ V: 8 row-groups x 32 d-lanes; write bf16 hi/lo split ----
    const int d = t & 31, ig = t >> 5;
    const size_t obase = (size_t)w * NN * 256 + h * HD + d;
    for (int i = ig; i < NN; i += 8) {
        float acc = 0.f;
#pragma unroll
        for (int j = 0; j < NN; j++)
            acc += sS[i * 52 + j] * vs[j * HD + d];
        __nv_bfloat16 hi = __float2bfloat16(acc);
        __nv_bfloat16 lo = __float2bfloat16(acc - __bfloat162float(hi));
        g_ahi[obase + (size_t)i * 256] = hi;
        g_alo[obase + (size_t)i * 256] = lo;
    }
}

// =====================================================================
extern "C" void kernel_launch(void* const* d_in, const int* in_sizes, int n_in,
                              void* d_out, int out_size) {
    const float* x     = (const float*)d_in[0];
    const float* qkvw  = (const float*)d_in[1];
    const float* qkvb  = (const float*)d_in[2];
    const float* projw = (const float*)d_in[3];
    const float* projb = (const float*)d_in[4];
    const float* tbl   = (const float*)d_in[5];
    const int*   ridx  = (const int*)d_in[6];
    float* out = (float*)d_out;

    (void)in_sizes; (void)n_in; (void)out_size;

    cudaFuncSetAttribute(wgemm<true>,  cudaFuncAttributeMaxDynamicSharedMemorySize, GM_SMEM);
    cudaFuncSetAttribute(wgemm<false>, cudaFuncAttributeMaxDynamicSharedMemorySize, GM_SMEM);

    bias_kernel<<<32, 256>>>(tbl, ridx);
    convsplit<0><<<XN / 4 / 256, 256>>>(x, XN / 4);
    convsplit<1><<<(768 * 256) / 4 / 256, 256>>>(qkvw, (768 * 256) / 4);
    convsplit<2><<<(256 * 256) / 4 / 256, 256>>>(projw, (256 * 256) / 4);

    wgemm<true><<<dim3(6, MTOT / 128), 256, GM_SMEM>>>(qkvb, nullptr);
    attn_kernel<<<NWTOT * HEADS, 256>>>();
    wgemm<false><<<dim3(2, MTOT / 128), 256, GM_SMEM>>>(projb, out);
}